// round 1
// baseline (speedup 1.0000x reference)
#include <cuda_runtime.h>

#define N     8192
#define FIN   512
#define FO    64
#define NW    (N/32)          // 256 mask words per row
#define NEG_BIG (-9e15f)
#define INVN  (1.0f/8192.0f)

#define RT    64              // rows per main block
#define JT    64              // j tile
#define JCHUNK 256            // j per block

// ---- scratch (static device arrays; no allocation) ----
__device__ float    g_Wh[N*FO];        // 2 MB
__device__ float    g_Wh1[N];
__device__ float    g_Wh2[N];
__device__ float    g_base[N];
__device__ float    g_km[N];
__device__ float    g_kn[N];
__device__ float    g_add[N];
__device__ unsigned g_mask[N*NW];      // 8 MB
__device__ unsigned g_maskn[N*NW];     // 8 MB
__device__ float    g_hp[N*FO];        // h_prime accumulator

// ============================================================
// Kernel 1: Wh = h @ W ; Wh1 = Wh@a[:64] ; Wh2 = Wh@a[64:]
// block: 256 threads = 4 rows x 64 cols
// ============================================================
__global__ void k_gemm1(const float* __restrict__ h,
                        const float* __restrict__ W,
                        const float* __restrict__ a) {
    __shared__ float a_s[2*FO];
    __shared__ float r1[4][2], r2[4][2];
    int t = threadIdx.x;
    if (t < 2*FO) a_s[t] = a[t];
    int row = t >> 6;                 // 0..3
    int f   = t & 63;
    int i   = blockIdx.x * 4 + row;
    __syncthreads();

    const float* hrow = h + (size_t)i * FIN;
    float acc = 0.f;
    #pragma unroll 4
    for (int k = 0; k < FIN; k += 4) {
        float4 hv = *reinterpret_cast<const float4*>(hrow + k);
        acc += hv.x * W[(k+0)*FO + f];
        acc += hv.y * W[(k+1)*FO + f];
        acc += hv.z * W[(k+2)*FO + f];
        acc += hv.w * W[(k+3)*FO + f];
    }
    g_Wh[(size_t)i*FO + f] = acc;

    float p1 = acc * a_s[f];
    float p2 = acc * a_s[FO + f];
    #pragma unroll
    for (int off = 16; off; off >>= 1) {
        p1 += __shfl_down_sync(0xffffffffu, p1, off);
        p2 += __shfl_down_sync(0xffffffffu, p2, off);
    }
    int w = t >> 5;
    if ((t & 31) == 0) { r1[w>>1][w&1] = p1; r2[w>>1][w&1] = p2; }
    __syncthreads();
    if (t < 4) {
        g_Wh1[blockIdx.x*4 + t] = r1[t][0] + r1[t][1];
        g_Wh2[blockIdx.x*4 + t] = r2[t][0] + r2[t][1];
    }
}

// ============================================================
// Kernel 2: one pass over adj / adj_new:
//  - ballot-pack to bitmasks
//  - online softmax stats (max,sum) per row for both masks
//  - also zeroes g_hp
// block: 256 threads = 8 warps = 8 rows; grid N/8
// ============================================================
__device__ __forceinline__ void online_upd(float e, float& m, float& s) {
    if (e > m) { s = s * __expf(m - e) + 1.f; m = e; }
    else       { s += __expf(e - m); }
}

__global__ void k_stats(const int* __restrict__ adj,
                        const int* __restrict__ adjn) {
    int tid = blockIdx.x * 256 + threadIdx.x;
    g_hp[2*tid]     = 0.f;          // 1024*256*2 = N*FO exactly
    g_hp[2*tid + 1] = 0.f;

    int lane = threadIdx.x & 31;
    int i    = blockIdx.x * 8 + (threadIdx.x >> 5);
    float wh1 = g_Wh1[i];
    const int* arow = adj  + (size_t)i * N;
    const int* nrow = adjn + (size_t)i * N;

    float mm = NEG_BIG, sm = 0.f, mn = NEG_BIG, sn = 0.f;
    for (int k = 0; k < NW; k++) {
        int j = k*32 + lane;
        bool bm = arow[j] > 0;
        bool bn = nrow[j] > 0;
        if (bm || bn) {
            float e = wh1 + g_Wh2[j];
            e = e > 0.f ? e : 0.2f * e;     // LeakyReLU
            if (bm) online_upd(e, mm, sm);
            if (bn) online_upd(e, mn, sn);
        }
        unsigned wm = __ballot_sync(0xffffffffu, bm);
        unsigned wn = __ballot_sync(0xffffffffu, bn);
        if (lane == 0) {
            g_mask [(size_t)i*NW + k] = wm;
            g_maskn[(size_t)i*NW + k] = wn;
        }
    }
    // warp tree-merge of (max,sum) pairs
    #pragma unroll
    for (int off = 16; off; off >>= 1) {
        float m2 = __shfl_xor_sync(0xffffffffu, mm, off);
        float s2 = __shfl_xor_sync(0xffffffffu, sm, off);
        float M  = fmaxf(mm, m2);
        sm = sm * __expf(mm - M) + s2 * __expf(m2 - M);
        mm = M;
        m2 = __shfl_xor_sync(0xffffffffu, mn, off);
        s2 = __shfl_xor_sync(0xffffffffu, sn, off);
        M  = fmaxf(mn, m2);
        sn = sn * __expf(mn - M) + s2 * __expf(m2 - M);
        mn = M;
    }
    if (lane == 0) {
        float base = fmaxf(mm, mn);
        g_base[i] = base;
        g_km[i]  = (sm > 0.f) ? __expf(base - mm) / sm : 0.f;
        g_kn[i]  = (sn > 0.f) ? __expf(base - mn) / sn : 0.f;
        g_add[i] = ((sm > 0.f) ? 0.f : INVN) + ((sn > 0.f) ? 0.f : INVN);
    }
}

// ============================================================
// Kernel 3: per (64-row, 256-j) block:
//   build 64x64 attention tile in SMEM -> write to gmem ->
//   accumulate h_prime partial with 4x8 register blocking ->
//   atomicAdd into g_hp.
// block: 128 threads; grid (N/JCHUNK, N/RT) = (32, 128)
// ============================================================
__global__ void __launch_bounds__(128) k_main(float* __restrict__ attn) {
    __shared__ float wh1_s[RT], base_s[RT], km_s[RT], kn_s[RT], add_s[RT];
    __shared__ float wh2_s[JT];
    __shared__ float Whs[JT][68];    // padded
    __shared__ float at_s[JT][68];   // attention tile, transposed [jj][i]

    int t   = threadIdx.x;
    int i0  = blockIdx.y * RT;
    int jc0 = blockIdx.x * JCHUNK;

    if (t < RT) {
        wh1_s[t]  = g_Wh1[i0+t];
        base_s[t] = g_base[i0+t];
        km_s[t]   = g_km[i0+t];
        kn_s[t]   = g_kn[i0+t];
        add_s[t]  = g_add[i0+t];
    }

    float acc[4][8];
    #pragma unroll
    for (int r = 0; r < 4; r++)
        #pragma unroll
        for (int c = 0; c < 8; c++) acc[r][c] = 0.f;

    int ri = t >> 3;      // 0..15 -> rows ri*4 .. ri*4+3
    int cg = t & 7;       // cols cg*4..+3 and 32+cg*4..+3
    int ai = t & 63;      // a-tile row
    int jh = t >> 6;      // a-tile j half

    for (int tt = 0; tt < JCHUNK/JT; tt++) {
        int j0 = jc0 + tt*JT;

        // load Wh tile (64x64) vectorized
        #pragma unroll
        for (int q = 0; q < 8; q++) {
            int idx = t + 128*q;            // 0..1023 float4 slots
            int r   = idx >> 4;
            int c4  = (idx & 15) * 4;
            *reinterpret_cast<float4*>(&Whs[r][c4]) =
                *reinterpret_cast<const float4*>(&g_Wh[(size_t)(j0 + r)*FO + c4]);
        }
        if (t < JT) wh2_s[t] = g_Wh2[j0 + t];
        __syncthreads();

        // compute attention tile: thread -> (row ai, 32 j's of half jh)
        {
            float wh1 = wh1_s[ai], base = base_s[ai];
            float km  = km_s[ai],  kn  = kn_s[ai], add = add_s[ai];
            unsigned mw = g_mask [(size_t)(i0+ai)*NW + (j0>>5) + jh];
            unsigned nw = g_maskn[(size_t)(i0+ai)*NW + (j0>>5) + jh];
            #pragma unroll 4
            for (int k = 0; k < 32; k++) {
                int jj  = jh*32 + k;
                float e = wh1 + wh2_s[jj];
                e = e > 0.f ? e : 0.2f * e;
                float w = (((mw>>k)&1u) ? km : 0.f) + (((nw>>k)&1u) ? kn : 0.f);
                float av = add + ((w != 0.f) ? __expf(e - base) * w : 0.f);
                at_s[jj][ai] = av;
            }
        }
        __syncthreads();

        // write attention to gmem, coalesced (warp = 32 consecutive j of one row)
        #pragma unroll 8
        for (int q = 0; q < 32; q++) {
            int idx = t + 128*q;            // 0..4095
            int ii  = idx >> 6;
            int jj  = idx & 63;
            attn[(size_t)(i0+ii)*N + j0 + jj] = at_s[jj][ii];
        }

        // FMA: acc[r][c] over this j tile
        #pragma unroll 8
        for (int jj = 0; jj < JT; jj++) {
            float4 av = *reinterpret_cast<const float4*>(&at_s[jj][ri*4]);
            float4 w0 = *reinterpret_cast<const float4*>(&Whs[jj][cg*4]);
            float4 w1 = *reinterpret_cast<const float4*>(&Whs[jj][32 + cg*4]);
            float avv[4] = {av.x, av.y, av.z, av.w};
            float wv[8]  = {w0.x, w0.y, w0.z, w0.w, w1.x, w1.y, w1.z, w1.w};
            #pragma unroll
            for (int r = 0; r < 4; r++)
                #pragma unroll
                for (int c = 0; c < 8; c++)
                    acc[r][c] += avv[r] * wv[c];
        }
        __syncthreads();
    }

    // merge partials
    #pragma unroll
    for (int r = 0; r < 4; r++) {
        size_t gi = (size_t)(i0 + ri*4 + r) * FO;
        #pragma unroll
        for (int c = 0; c < 4; c++) {
            atomicAdd(&g_hp[gi + cg*4 + c],      acc[r][c]);
            atomicAdd(&g_hp[gi + 32 + cg*4 + c], acc[r][4+c]);
        }
    }
}

// ============================================================
// Kernel 4: out = elu(h_prime)
// ============================================================
__global__ void k_elu(float* __restrict__ out) {
    int tid = blockIdx.x * 256 + threadIdx.x;
    float x = g_hp[tid];
    out[tid] = x > 0.f ? x : expm1f(x);
}

// ============================================================
extern "C" void kernel_launch(void* const* d_in, const int* in_sizes, int n_in,
                              void* d_out, int out_size) {
    const float* h    = (const float*)d_in[0];
    const float* W    = (const float*)d_in[1];
    const float* a    = (const float*)d_in[2];
    const int*   adj  = (const int*)d_in[3];
    const int*   adjn = (const int*)d_in[4];

    float* out  = (float*)d_out;
    float* attn = out + (size_t)N * FO;   // [out | attention]

    k_gemm1<<<N/4, 256>>>(h, W, a);
    k_stats<<<N/8, 256>>>(adj, adjn);
    k_main<<<dim3(N/JCHUNK, N/RT), 128>>>(attn);
    k_elu<<<(N*FO)/256, 256>>>(out);
}

// round 3
// speedup vs baseline: 1.7066x; 1.7066x over previous
#include <cuda_runtime.h>
#include <cstdint>

#define N     8192
#define FIN   512
#define FO    64
#define NW    256             // mask words per row
#define NEG_BIG (-9e15f)
#define INVN  (1.0f/8192.0f)
#define KS    4               // K-splits in k_main

// ---- scratch ----
__device__ float    g_Wh[N*FO];
__device__ float    g_Wh1[N];
__device__ float    g_Wh2[N];
__device__ float    g_B[N];           // exp(wh2)
__device__ float    g_D[N];           // exp(0.2*wh2)
__device__ float    g_add[N];
__device__ float    g_cpm[N], g_ncm[N], g_cpn[N], g_ncn[N];
__device__ unsigned g_mask[N*NW];
__device__ unsigned g_maskn[N*NW];
__device__ float    g_hp[N*FO];

__device__ __forceinline__ uint32_t tf32bits(float x) {
    uint32_t r; asm("cvt.rna.tf32.f32 %0, %1;" : "=r"(r) : "f"(x)); return r;
}
__device__ __forceinline__ void mma_tf32(float* d,
        uint32_t a0, uint32_t a1, uint32_t a2, uint32_t a3,
        uint32_t b0, uint32_t b1) {
    asm volatile("mma.sync.aligned.m16n8k8.row.col.f32.tf32.tf32.f32 "
        "{%0,%1,%2,%3}, {%4,%5,%6,%7}, {%8,%9}, {%0,%1,%2,%3};"
        : "+f"(d[0]), "+f"(d[1]), "+f"(d[2]), "+f"(d[3])
        : "r"(a0), "r"(a1), "r"(a2), "r"(a3), "r"(b0), "r"(b1));
}

// ============================================================
// Kernel 1: Wh = h @ W ; Wh1 ; Wh2
// ============================================================
__global__ void k_gemm1(const float* __restrict__ h,
                        const float* __restrict__ W,
                        const float* __restrict__ a) {
    __shared__ float a_s[2*FO];
    __shared__ float r1[8][2], r2[8][2];
    int t = threadIdx.x;
    if (t < 2*FO) a_s[t] = a[t];
    int row = t >> 6;
    int f   = t & 63;
    int i   = blockIdx.x * 8 + row;
    __syncthreads();

    const float* hrow = h + (size_t)i * FIN;
    float acc = 0.f;
    #pragma unroll 4
    for (int k = 0; k < FIN; k += 4) {
        float4 hv = *reinterpret_cast<const float4*>(hrow + k);
        acc += hv.x * W[(k+0)*FO + f];
        acc += hv.y * W[(k+1)*FO + f];
        acc += hv.z * W[(k+2)*FO + f];
        acc += hv.w * W[(k+3)*FO + f];
    }
    g_Wh[(size_t)i*FO + f] = acc;

    float p1 = acc * a_s[f];
    float p2 = acc * a_s[FO + f];
    #pragma unroll
    for (int off = 16; off; off >>= 1) {
        p1 += __shfl_down_sync(0xffffffffu, p1, off);
        p2 += __shfl_down_sync(0xffffffffu, p2, off);
    }
    int w = t >> 5;
    if ((t & 31) == 0) { r1[w>>1][w&1] = p1; r2[w>>1][w&1] = p2; }
    __syncthreads();
    if (t < 8) {
        g_Wh1[blockIdx.x*8 + t] = r1[t][0] + r1[t][1];
        g_Wh2[blockIdx.x*8 + t] = r2[t][0] + r2[t][1];
    }
}

// ============================================================
// Kernel 1b: B[j] = exp(wh2_j), D[j] = exp(0.2 wh2_j)
// ============================================================
__global__ void k_prep() {
    int tid = blockIdx.x * 256 + threadIdx.x;
    float w2 = g_Wh2[tid];
    g_B[tid] = expf(w2);
    g_D[tid] = expf(0.2f * w2);
}

// ============================================================
// Kernel 2: one adj pass -> bitmasks + per-row softmax coefs
// (no exp in inner loop: max of e is monotone in wh2; sums use B/D)
// block: 256 thr = 8 warps = 8 rows; grid N/8
// ============================================================
__global__ void k_stats(const int* __restrict__ adj,
                        const int* __restrict__ adjn) {
    int tid = blockIdx.x * 256 + threadIdx.x;
    g_hp[2*tid]     = 0.f;
    g_hp[2*tid + 1] = 0.f;

    int lane = threadIdx.x & 31;
    int i    = blockIdx.x * 8 + (threadIdx.x >> 5);
    float wh1 = g_Wh1[i];
    float thr = -wh1;
    const int* arow = adj  + (size_t)i * N;
    const int* nrow = adjn + (size_t)i * N;

    float Mm = NEG_BIG, Mn = NEG_BIG;
    float Smp = 0.f, Smn = 0.f, Snp = 0.f, Snn = 0.f;

    for (int k = 0; k < N/128; k++) {
        int jb = k*128 + lane*4;
        int4   av = *reinterpret_cast<const int4*>(&arow[jb]);
        int4   nv = *reinterpret_cast<const int4*>(&nrow[jb]);
        float4 w2 = *reinterpret_cast<const float4*>(&g_Wh2[jb]);
        float4 Bv = *reinterpret_cast<const float4*>(&g_B[jb]);
        float4 Dv = *reinterpret_cast<const float4*>(&g_D[jb]);

        unsigned nm = 0, nn = 0;
        {
            bool bm = av.x > 0, bn = nv.x > 0, p = w2.x > thr;
            if (bm) { Mm = fmaxf(Mm, w2.x); if (p) Smp += Bv.x; else Smn += Dv.x; nm |= 1u; }
            if (bn) { Mn = fmaxf(Mn, w2.x); if (p) Snp += Bv.x; else Snn += Dv.x; nn |= 1u; }
        }
        {
            bool bm = av.y > 0, bn = nv.y > 0, p = w2.y > thr;
            if (bm) { Mm = fmaxf(Mm, w2.y); if (p) Smp += Bv.y; else Smn += Dv.y; nm |= 2u; }
            if (bn) { Mn = fmaxf(Mn, w2.y); if (p) Snp += Bv.y; else Snn += Dv.y; nn |= 2u; }
        }
        {
            bool bm = av.z > 0, bn = nv.z > 0, p = w2.z > thr;
            if (bm) { Mm = fmaxf(Mm, w2.z); if (p) Smp += Bv.z; else Smn += Dv.z; nm |= 4u; }
            if (bn) { Mn = fmaxf(Mn, w2.z); if (p) Snp += Bv.z; else Snn += Dv.z; nn |= 4u; }
        }
        {
            bool bm = av.w > 0, bn = nv.w > 0, p = w2.w > thr;
            if (bm) { Mm = fmaxf(Mm, w2.w); if (p) Smp += Bv.w; else Smn += Dv.w; nm |= 8u; }
            if (bn) { Mn = fmaxf(Mn, w2.w); if (p) Snp += Bv.w; else Snn += Dv.w; nn |= 8u; }
        }
        unsigned vm = nm << ((lane & 7) * 4);
        unsigned vn = nn << ((lane & 7) * 4);
        vm |= __shfl_xor_sync(0xffffffffu, vm, 1);
        vn |= __shfl_xor_sync(0xffffffffu, vn, 1);
        vm |= __shfl_xor_sync(0xffffffffu, vm, 2);
        vn |= __shfl_xor_sync(0xffffffffu, vn, 2);
        vm |= __shfl_xor_sync(0xffffffffu, vm, 4);
        vn |= __shfl_xor_sync(0xffffffffu, vn, 4);
        if ((lane & 7) == 0) {
            g_mask [(size_t)i*NW + k*4 + (lane>>3)] = vm;
            g_maskn[(size_t)i*NW + k*4 + (lane>>3)] = vn;
        }
    }
    // warp reduce
    #pragma unroll
    for (int off = 16; off; off >>= 1) {
        Mm  = fmaxf(Mm, __shfl_xor_sync(0xffffffffu, Mm, off));
        Mn  = fmaxf(Mn, __shfl_xor_sync(0xffffffffu, Mn, off));
        Smp += __shfl_xor_sync(0xffffffffu, Smp, off);
        Smn += __shfl_xor_sync(0xffffffffu, Smn, off);
        Snp += __shfl_xor_sync(0xffffffffu, Snp, off);
        Snn += __shfl_xor_sync(0xffffffffu, Snn, off);
    }
    if (lane == 0) {
        bool hasm = Mm > 0.5f*NEG_BIG, hasn = Mn > 0.5f*NEG_BIG;
        float Mu = fmaxf(Mm, Mn);
        float x  = wh1 + Mu;
        float base = (hasm || hasn) ? (x > 0.f ? x : 0.2f * x) : 0.f;
        float ep = expf(wh1 - base);
        float en = expf(0.2f * wh1 - base);
        float dm = ep * Smp + en * Smn;        // sum exp(e-base) over adj
        float dn = ep * Snp + en * Snn;
        float km = (dm > 0.f) ? 1.f / dm : 0.f;
        float kn = (dn > 0.f) ? 1.f / dn : 0.f;
        g_add[i] = ((dm > 0.f) ? 0.f : INVN) + ((dn > 0.f) ? 0.f : INVN);
        g_cpm[i] = ep * km;  g_ncm[i] = en * km;
        g_cpn[i] = ep * kn;  g_ncn[i] = en * kn;
    }
}

// ============================================================
// Kernel 3: fused attention + tf32 mma.sync (attn @ Wh)
// grid (KS, N/128); 256 thr = 8 warps; warp w -> 16 rows
// ============================================================
__device__ __forceinline__ float attn_val(float w2, float Bj, float Dj,
        float thr, float add, float cpm, float ncm, float cpn, float ncn,
        unsigned mb, unsigned nb) {
    bool  p  = w2 > thr;
    float E  = p ? Bj : Dj;
    float cm = p ? cpm : ncm;
    float cn = p ? cpn : ncn;
    float wg = ((mb & 1u) ? cm : 0.f) + ((nb & 1u) ? cn : 0.f);
    return fmaf(E, wg, add);
}

__global__ void __launch_bounds__(256, 2) k_main(float* __restrict__ attn) {
    __shared__ uint32_t whs[64*72];            // tf32 Wh tile, padded
    __shared__ float    Bs[64], Ds[64], w2s[64];

    int t = threadIdx.x, w = t >> 5, lane = t & 31;
    int g = lane >> 2, c = lane & 3;
    int i0 = blockIdx.y * 128;
    int r0 = i0 + w*16 + g, r1 = r0 + 8;

    float thr0 = -g_Wh1[r0],  thr1 = -g_Wh1[r1];
    float add0 = g_add[r0],   add1 = g_add[r1];
    float cpm0 = g_cpm[r0], ncm0 = g_ncm[r0], cpn0 = g_cpn[r0], ncn0 = g_ncn[r0];
    float cpm1 = g_cpm[r1], ncm1 = g_ncm[r1], cpn1 = g_cpn[r1], ncn1 = g_ncn[r1];

    float acc[8][4];
    #pragma unroll
    for (int nt = 0; nt < 8; nt++)
        #pragma unroll
        for (int q = 0; q < 4; q++) acc[nt][q] = 0.f;

    int jcta = blockIdx.x * (N/KS);

    for (int tt = 0; tt < (N/KS)/64; tt++) {
        int j0 = jcta + tt*64;
        __syncthreads();
        // stage Wh tile (64x64) as tf32, row pad 72
        #pragma unroll
        for (int q = 0; q < 4; q++) {
            int idx = t + 256*q;
            int r = idx >> 4, c4 = (idx & 15) * 4;
            float4 v = *reinterpret_cast<const float4*>(&g_Wh[(size_t)(j0+r)*FO + c4]);
            uint32_t* p = &whs[r*72 + c4];
            p[0] = tf32bits(v.x); p[1] = tf32bits(v.y);
            p[2] = tf32bits(v.z); p[3] = tf32bits(v.w);
        }
        if (t < 64) { Bs[t] = g_B[j0+t]; Ds[t] = g_D[j0+t]; w2s[t] = g_Wh2[j0+t]; }
        __syncthreads();

        int wb = j0 >> 5;
        uint2 mw0 = *reinterpret_cast<const uint2*>(&g_mask [(size_t)r0*NW + wb]);
        uint2 nw0 = *reinterpret_cast<const uint2*>(&g_maskn[(size_t)r0*NW + wb]);
        uint2 mw1 = *reinterpret_cast<const uint2*>(&g_mask [(size_t)r1*NW + wb]);
        uint2 nw1 = *reinterpret_cast<const uint2*>(&g_maskn[(size_t)r1*NW + wb]);

        size_t o0 = (size_t)r0*N + j0;
        size_t o1 = (size_t)r1*N + j0;

        #pragma unroll
        for (int kk = 0; kk < 8; kk++) {
            int jA = kk*8 + c, jB = jA + 4;
            float BA = Bs[jA], DA = Ds[jA], wA = w2s[jA];
            float BB = Bs[jB], DB = Ds[jB], wB = w2s[jB];
            unsigned m0 = (kk < 4) ? mw0.x : mw0.y;
            unsigned n0 = (kk < 4) ? nw0.x : nw0.y;
            unsigned m1 = (kk < 4) ? mw1.x : mw1.y;
            unsigned n1 = (kk < 4) ? nw1.x : nw1.y;
            int sA = (kk & 3)*8 + c, sB = sA + 4;

            float v00 = attn_val(wA, BA, DA, thr0, add0, cpm0, ncm0, cpn0, ncn0, m0>>sA, n0>>sA);
            float v10 = attn_val(wA, BA, DA, thr1, add1, cpm1, ncm1, cpn1, ncn1, m1>>sA, n1>>sA);
            float v01 = attn_val(wB, BB, DB, thr0, add0, cpm0, ncm0, cpn0, ncn0, m0>>sB, n0>>sB);
            float v11 = attn_val(wB, BB, DB, thr1, add1, cpm1, ncm1, cpn1, ncn1, m1>>sB, n1>>sB);

            attn[o0 + jA] = v00;  attn[o0 + jB] = v01;
            attn[o1 + jA] = v10;  attn[o1 + jB] = v11;

            uint32_t a0 = tf32bits(v00), a1 = tf32bits(v10);
            uint32_t a2 = tf32bits(v01), a3 = tf32bits(v11);

            int rowA = jA*72, rowB = jB*72;
            #pragma unroll
            for (int nt = 0; nt < 8; nt++) {
                uint32_t b0 = whs[rowA + nt*8 + g];
                uint32_t b1 = whs[rowB + nt*8 + g];
                mma_tf32(acc[nt], a0, a1, a2, a3, b0, b1);
            }
        }
    }

    #pragma unroll
    for (int nt = 0; nt < 8; nt++) {
        atomicAdd(&g_hp[(size_t)r0*FO + nt*8 + 2*c    ], acc[nt][0]);
        atomicAdd(&g_hp[(size_t)r0*FO + nt*8 + 2*c + 1], acc[nt][1]);
        atomicAdd(&g_hp[(size_t)r1*FO + nt*8 + 2*c    ], acc[nt][2]);
        atomicAdd(&g_hp[(size_t)r1*FO + nt*8 + 2*c + 1], acc[nt][3]);
    }
}

// ============================================================
// Kernel 4: out = elu(h_prime)
// ============================================================
__global__ void k_elu(float* __restrict__ out) {
    int tid = blockIdx.x * 256 + threadIdx.x;
    float x = g_hp[tid];
    out[tid] = x > 0.f ? x : expm1f(x);
}

// ============================================================
extern "C" void kernel_launch(void* const* d_in, const int* in_sizes, int n_in,
                              void* d_out, int out_size) {
    const float* h    = (const float*)d_in[0];
    const float* W    = (const float*)d_in[1];
    const float* a    = (const float*)d_in[2];
    const int*   adj  = (const int*)d_in[3];
    const int*   adjn = (const int*)d_in[4];

    float* out  = (float*)d_out;
    float* attn = out + (size_t)N * FO;

    k_gemm1<<<N/8, 512>>>(h, W, a);
    k_prep<<<N/256, 256>>>();
    k_stats<<<N/8, 256>>>(adj, adjn);
    k_main<<<dim3(KS, N/128), 256>>>(attn);
    k_elu<<<(N*FO)/256, 256>>>(out);
}